// round 2
// baseline (speedup 1.0000x reference)
#include <cuda_runtime.h>
#include <cstdint>

// Problem constants
#define BB   4096
#define TT   256
#define II   7
#define HH   64
#define OO   8
#define BETA 0.8f

// ---- scan kernel config: 2 neurons/thread, warp == one batch ----
#define NBATCH   8          // batches per block
#define SCAN_NT  256        // NBATCH * 32 threads
#define TCHUNK   128        // timesteps staged per chunk

// spike masks scratch: (even-h word, odd-h word) per (b,t)  -> 8 MB
__device__ uint2 g_masks[(size_t)BB * TT];

__global__ __launch_bounds__(SCAN_NT) void snn_scan(
    const float* __restrict__ x,    // (B, T, I)
    const float* __restrict__ h0,   // (B, 1, H)
    const float* __restrict__ W1,   // (H, I)
    const float* __restrict__ b1,   // (H,)
    float* __restrict__ hid)        // (B, T, H)
{
    // x chunk, padded to 8 floats per t for LDS.128
    __shared__ float xs[NBATCH * TCHUNK * 8];     // 32 KB

    const int tid  = threadIdx.x;
    const int lane = tid & 31;
    const int bl   = tid >> 5;                    // local batch = warp id
    const int b0   = blockIdx.x * NBATCH;
    const int b    = b0 + bl;
    const int hE   = lane * 2;                    // even neuron
    // odd neuron = hE + 1

    // per-thread W1 rows + biases for the two neurons
    float w1a[II], w1b[II];
#pragma unroll
    for (int i = 0; i < II; ++i) {
        w1a[i] = W1[hE * II + i];
        w1b[i] = W1[(hE + 1) * II + i];
    }
    const float biasA = b1[hE];
    const float biasB = b1[hE + 1];

    // LIF state (reset_t == spike_{t-1})
    float memA = h0[(size_t)b * HH + hE];
    float memB = h0[(size_t)b * HH + hE + 1];
    float sA = (memA > 1.0f) ? 1.0f : 0.0f;
    float sB = (memB > 1.0f) ? 1.0f : 0.0f;

    float2* hidp = (float2*)(hid + (size_t)b * TT * HH) + lane;  // stride 32 float2 per t
    uint2*  mp   = g_masks + (size_t)b * TT;

    uint32_t mev = 0, mod = 0;   // latched ballots for "my" step in the 32-window

    for (int chunk = 0; chunk < 2; ++chunk) {
        __syncthreads();
        {   // cooperative coalesced staging of x with pad-to-8 scatter
            const float* xg = x + ((size_t)b0 * TT + (size_t)chunk * TCHUNK) * II;
            for (int idx = tid; idx < NBATCH * TCHUNK * II; idx += SCAN_NT) {
                int lb = idx / (TCHUNK * II);
                int r  = idx - lb * (TCHUNK * II);
                int t  = r / II;
                int i  = r - t * II;
                xs[lb * TCHUNK * 8 + t * 8 + i] = xg[(size_t)lb * TT * II + r];
            }
        }
        __syncthreads();

        const float4* xq = (const float4*)(xs + bl * TCHUNK * 8);

#pragma unroll 4
        for (int tt = 0; tt < TCHUNK; ++tt) {
            float4 xa = xq[tt * 2];
            float4 xb = xq[tt * 2 + 1];   // .w is pad

            float curA = biasA, curB = biasB;
            curA = fmaf(xa.x, w1a[0], curA);  curB = fmaf(xa.x, w1b[0], curB);
            curA = fmaf(xa.y, w1a[1], curA);  curB = fmaf(xa.y, w1b[1], curB);
            curA = fmaf(xa.z, w1a[2], curA);  curB = fmaf(xa.z, w1b[2], curB);
            curA = fmaf(xa.w, w1a[3], curA);  curB = fmaf(xa.w, w1b[3], curB);
            curA = fmaf(xb.x, w1a[4], curA);  curB = fmaf(xb.x, w1b[4], curB);
            curA = fmaf(xb.y, w1a[5], curA);  curB = fmaf(xb.y, w1b[5], curB);
            curA = fmaf(xb.z, w1a[6], curA);  curB = fmaf(xb.z, w1b[6], curB);

            // mem = beta*mem + cur - spk_prev ; spk = mem > 1
            memA = fmaf(BETA, memA, curA) - sA;
            memB = fmaf(BETA, memB, curB) - sB;
            bool kA = memA > 1.0f;
            bool kB = memB > 1.0f;
            sA = kA ? 1.0f : 0.0f;
            sB = kB ? 1.0f : 0.0f;

            const int t = chunk * TCHUNK + tt;
            hidp[(size_t)t * (HH / 2)] = make_float2(memA, memB);   // coalesced 256B/warp

            uint32_t bev = __ballot_sync(0xFFFFFFFFu, kA);
            uint32_t bod = __ballot_sync(0xFFFFFFFFu, kB);
            if ((tt & 31) == lane) { mev = bev; mod = bod; }        // predicated latch
            if ((tt & 31) == 31) {                                   // coalesced flush / 32 steps
                mp[(t & ~31) + lane] = make_uint2(mev, mod);
            }
        }
    }
}

// ---- output kernel: nibble-table sparse decode ----
// mask words: ev bit j <-> h = 2j ; od bit j <-> h = 2j+1
// nibble group n (0..7 from ev word, 8..15 from od word), bit k in nibble:
//   n < 8 : h = 8n + 2k        n >= 8 : h = 8(n-8) + 2k + 1
#define P2_NT 256

__global__ __launch_bounds__(P2_NT) void snn_out(
    const float* __restrict__ W2,   // (O, H)
    const float* __restrict__ b2,   // (O,)
    float* __restrict__ out)        // (B, T, O)
{
    __shared__ float tbl[16 * 16 * 8];   // 8 KB: [group][combo][o]
    __shared__ float w2s[HH * OO];       // 2 KB: [h][o]

    const int tid = threadIdx.x;

    for (int j = tid; j < HH * OO; j += P2_NT) {
        int hh = j >> 3, oo = j & 7;
        w2s[j] = W2[oo * HH + hh];
    }
    __syncthreads();

    // one table entry per thread (256 entries)
    {
        int e = tid;            // e = g*16 + c
        int g = e >> 4;
        uint32_t c = e & 15;
        float a[8] = {0,0,0,0,0,0,0,0};
        uint32_t cc = c;
        while (cc) {
            int k = __ffs(cc) - 1; cc &= cc - 1;
            int hh = (g < 8) ? (8 * g + 2 * k) : (8 * (g - 8) + 2 * k + 1);
#pragma unroll
            for (int o = 0; o < 8; ++o) a[o] += w2s[hh * 8 + o];
        }
#pragma unroll
        for (int o = 0; o < 8; ++o) tbl[e * 8 + o] = a[o];
    }
    __syncthreads();

    const float c0 = b2[0], c1 = b2[1], c2 = b2[2], c3 = b2[3];
    const float c4 = b2[4], c5 = b2[5], c6 = b2[6], c7 = b2[7];

    const size_t total  = (size_t)BB * TT;
    const size_t stride = (size_t)gridDim.x * P2_NT;

    for (size_t idx = (size_t)blockIdx.x * P2_NT + tid; idx < total; idx += stride) {
        uint2 m = g_masks[idx];

        float a0 = c0, a1 = c1, a2 = c2, a3 = c3;
        float a4 = c4, a5 = c5, a6 = c6, a7 = c7;

#pragma unroll
        for (int g = 0; g < 8; ++g) {
            uint32_t c = (m.x >> (4 * g)) & 15u;
            if (c) {
                const float4* p = (const float4*)(tbl + (g * 16 + c) * 8);
                float4 lo = p[0], hi = p[1];
                a0 += lo.x; a1 += lo.y; a2 += lo.z; a3 += lo.w;
                a4 += hi.x; a5 += hi.y; a6 += hi.z; a7 += hi.w;
            }
        }
#pragma unroll
        for (int g = 0; g < 8; ++g) {
            uint32_t c = (m.y >> (4 * g)) & 15u;
            if (c) {
                const float4* p = (const float4*)(tbl + ((g + 8) * 16 + c) * 8);
                float4 lo = p[0], hi = p[1];
                a0 += lo.x; a1 += lo.y; a2 += lo.z; a3 += lo.w;
                a4 += hi.x; a5 += hi.y; a6 += hi.z; a7 += hi.w;
            }
        }

        float4* op = (float4*)(out + idx * OO);
        op[0] = make_float4(a0, a1, a2, a3);
        op[1] = make_float4(a4, a5, a6, a7);
    }
}

extern "C" void kernel_launch(void* const* d_in, const int* in_sizes, int n_in,
                              void* d_out, int out_size)
{
    const float* x  = (const float*)d_in[0];
    const float* h0 = (const float*)d_in[1];
    const float* W1 = (const float*)d_in[2];
    const float* b1 = (const float*)d_in[3];
    const float* W2 = (const float*)d_in[4];
    const float* b2 = (const float*)d_in[5];

    float* out = (float*)d_out;                       // outputs first ...
    float* hid = out + (size_t)BB * TT * OO;          // ... then new_hidden

    snn_scan<<<BB / NBATCH, SCAN_NT>>>(x, h0, W1, b1, hid);
    snn_out<<<1024, P2_NT>>>(W2, b2, out);
}